// round 2
// baseline (speedup 1.0000x reference)
#include <cuda_runtime.h>

// Correlation (FlowNet), max_displacement=40:
//   out[b, dy*81+dx, h, w] = (1/sqrt(128)) * sum_c x1[b,c,h,w] * x2pad[b,c,h+dy,w+dx]
// Shapes: x1,x2 = (2,128,64,96) f32; out = (2,6561,64,96) f32.

#define MD   40
#define KD   81         // 2*MD+1
#define C    128
#define H    64
#define W    96
#define WPS  192        // padded smem row for x2 window (>= W+2*MD+15, 16B-aligned stride)
#define NT   132        // 12 w-groups x 11 dx-groups
#define SMEM_BYTES ((C*W + C*WPS) * 4)   // 49152 + 98304 = 147456 B

__global__ __launch_bounds__(NT, 1)
void corr_kernel(const float* __restrict__ x1,
                 const float* __restrict__ x2,
                 float* __restrict__ out)
{
    extern __shared__ float sm[];
    float* s1 = sm;                 // [C][W]   x1 row at (b, h)
    float* s2 = sm + C * W;         // [C][WPS] zero-padded x2 row at (b, h+dy-MD)

    const int dy  = blockIdx.x;     // 0..80
    const int h   = blockIdx.y;     // 0..63
    const int b   = blockIdx.z;     // 0..1
    const int tid = threadIdx.x;

    const int h2 = h + dy - MD;     // source row in x2

    if (h2 < 0 || h2 >= H) {
        // Entire (b, h, dy, *) slab is zero: 81 dx rows of 96 floats.
        const size_t base = (((size_t)b * (KD * KD) + (size_t)dy * KD) * H + h) * W;
        for (int i = tid; i < KD * W; i += NT) {
            const int dx = i / W;
            const int w  = i % W;
            out[base + (size_t)dx * (H * W) + w] = 0.0f;
        }
        return;
    }

    // ---- stage x1 row and padded x2 row into shared memory ----
    const float* x1b = x1 + ((size_t)b * C * H + h)  * W;   // + c*H*W
    const float* x2b = x2 + ((size_t)b * C * H + h2) * W;   // + c*H*W

    for (int i = tid; i < C * W; i += NT) {
        const int c = i / W, w = i % W;
        s1[c * W + w] = x1b[(size_t)c * (H * W) + w];
    }
    for (int i = tid; i < C * WPS; i += NT) {
        const int c  = i / WPS;
        const int wp = i % WPS;
        const int wg = wp - MD;                 // global w in x2
        float v = 0.0f;
        if (wg >= 0 && wg < W) v = x2b[(size_t)c * (H * W) + wg];
        s2[c * WPS + wp] = v;
    }
    __syncthreads();

    // ---- register-tiled 1-D correlation: 8 dx x 8 w per thread ----
    const int wgi = tid % 12;       // w group
    const int dg  = tid / 12;       // dx group (0..10; last group only dx=80 valid)
    const int w0  = wgi * 8;
    const int dx0 = dg * 8;

    float acc[8][8];
#pragma unroll
    for (int d = 0; d < 8; ++d)
#pragma unroll
        for (int i = 0; i < 8; ++i) acc[d][i] = 0.0f;

    const float* p1 = s1 + w0;              // 32B-aligned (w0 % 8 == 0)
    const float* p2 = s2 + w0 + dx0;        // 32B-aligned ((w0+dx0) % 8 == 0)

#pragma unroll 2
    for (int c = 0; c < C; ++c) {
        const float* r1 = p1 + c * W;
        const float* r2 = p2 + c * WPS;

        const float4 a0 = *(const float4*)(r1);
        const float4 a1 = *(const float4*)(r1 + 4);
        const float4 b0 = *(const float4*)(r2);
        const float4 b1 = *(const float4*)(r2 + 4);
        const float4 b2 = *(const float4*)(r2 + 8);
        const float4 b3 = *(const float4*)(r2 + 12);

        const float a[8]  = {a0.x, a0.y, a0.z, a0.w, a1.x, a1.y, a1.z, a1.w};
        const float bw[16] = {b0.x, b0.y, b0.z, b0.w,
                              b1.x, b1.y, b1.z, b1.w,
                              b2.x, b2.y, b2.z, b2.w,
                              b3.x, b3.y, b3.z, b3.w};

#pragma unroll
        for (int d = 0; d < 8; ++d)
#pragma unroll
            for (int i = 0; i < 8; ++i)
                acc[d][i] = fmaf(a[i], bw[d + i], acc[d][i]);
    }

    // ---- write back: out[b, dy*81+dx, h, w0..w0+7] ----
    const float scale = 0.08838834764831843f;   // 1/sqrt(128)
#pragma unroll
    for (int d = 0; d < 8; ++d) {
        const int dx = dx0 + d;
        if (dx < KD) {
            const size_t o = (((size_t)b * (KD * KD) + (size_t)(dy * KD + dx)) * H + h) * W + w0;
            float4 v0, v1;
            v0.x = acc[d][0] * scale; v0.y = acc[d][1] * scale;
            v0.z = acc[d][2] * scale; v0.w = acc[d][3] * scale;
            v1.x = acc[d][4] * scale; v1.y = acc[d][5] * scale;
            v1.z = acc[d][6] * scale; v1.w = acc[d][7] * scale;
            *(float4*)(out + o)     = v0;
            *(float4*)(out + o + 4) = v1;
        }
    }
}

extern "C" void kernel_launch(void* const* d_in, const int* in_sizes, int n_in,
                              void* d_out, int out_size)
{
    const float* x1 = (const float*)d_in[0];
    const float* x2 = (const float*)d_in[1];
    float* out = (float*)d_out;

    // Idempotent, non-stream API call: needed for 144 KB dynamic smem.
    cudaFuncSetAttribute(corr_kernel, cudaFuncAttributeMaxDynamicSharedMemorySize, SMEM_BYTES);

    dim3 grid(KD, H, 2);     // (dy, h, b)
    corr_kernel<<<grid, NT, SMEM_BYTES>>>(x1, x2, out);
}

// round 4
// speedup vs baseline: 1.5623x; 1.5623x over previous
#include <cuda_runtime.h>

// Correlation (FlowNet), max_displacement=40:
//   out[b, dy*81+dx, h, w] = (1/sqrt(128)) * sum_c x1[b,c,h,w] * x2pad[b,c,h+dy,w+dx]
// x1,x2 = (2,128,64,96) f32; out = (2,6561,64,96) f32.
//
// R2 (resubmit after infra failure): 264 threads (2-way C-split per tile) +
// packed fp32 FMA (fma.rn.f32x2 -> FFMA2) + wgi-major tile->lane mapping for
// smem broadcast/dedup.

#define MD    40
#define KD    81          // 2*MD+1
#define C     128
#define H     64
#define W     96
#define WPS   192         // padded smem row stride for x2 window
#define NTILE 132         // 12 w-groups * 11 dx-groups
#define NT    264         // NTILE * 2 c-chunks
#define SMEM_BYTES ((C*W + C*WPS) * 4)   // 147456 B

typedef unsigned long long u64;

__device__ __forceinline__ u64 pack2(float lo, float hi) {
    u64 r; asm("mov.b64 %0, {%1, %2};" : "=l"(r) : "f"(lo), "f"(hi)); return r;
}
__device__ __forceinline__ void fma2(u64& d, u64 a, u64 b) {
    asm("fma.rn.f32x2 %0, %1, %2, %0;" : "+l"(d) : "l"(a), "l"(b));
}
__device__ __forceinline__ float2 unpack2(u64 v) {
    float2 r; asm("mov.b64 {%0, %1}, %2;" : "=f"(r.x), "=f"(r.y) : "l"(v)); return r;
}

__global__ __launch_bounds__(NT, 1)
void corr_kernel(const float* __restrict__ x1,
                 const float* __restrict__ x2,
                 float* __restrict__ out)
{
    extern __shared__ float sm[];
    float* s1 = sm;                 // [C][W]   x1 row at (b, h)
    float* s2 = sm + C * W;         // [C][WPS] zero-padded x2 row at (b, h+dy-MD)

    const int dy  = blockIdx.x;     // 0..80
    const int h   = blockIdx.y;     // 0..63
    const int b   = blockIdx.z;     // 0..1
    const int tid = threadIdx.x;

    const int h2 = h + dy - MD;

    if (h2 < 0 || h2 >= H) {
        // Entire (b, h, dy, *) slab is zero: 81 dx rows of 96 floats (vectorized).
        const size_t base = (((size_t)b * (KD * KD) + (size_t)dy * KD) * H + h) * W;
        const float4 z = make_float4(0.f, 0.f, 0.f, 0.f);
        for (int i = tid; i < KD * (W / 4); i += NT) {
            const int dx = i / (W / 4);
            const int w4 = i % (W / 4);
            *(float4*)(out + base + (size_t)dx * (H * W) + w4 * 4) = z;
        }
        return;
    }

    // ---- stage x1 row and padded x2 row into shared memory (float4) ----
    const float* x1b = x1 + ((size_t)b * C * H + h)  * W;
    const float* x2b = x2 + ((size_t)b * C * H + h2) * W;

    for (int i = tid; i < C * (W / 4); i += NT) {
        const int c = i / (W / 4), q = i % (W / 4);
        *(float4*)(s1 + c * W + q * 4) = *(const float4*)(x1b + (size_t)c * (H * W) + q * 4);
    }
    const float4 z4 = make_float4(0.f, 0.f, 0.f, 0.f);
    for (int i = tid; i < C * (WPS / 4); i += NT) {
        const int c = i / (WPS / 4), q = i % (WPS / 4);
        // valid scalar range wp in [MD, MD+W) = [40,136) -> float4 chunks 10..33
        float4 v = z4;
        if (q >= MD / 4 && q < (MD + W) / 4)
            v = *(const float4*)(x2b + (size_t)c * (H * W) + (q * 4 - MD));
        *(float4*)(s2 + c * WPS + q * 4) = v;
    }
    __syncthreads();

    // ---- tile / c-chunk mapping ----
    // tile = wgi*11 + dg  (dg fastest within a warp -> same wgi lanes share x1,
    // and equal wgi+dg lanes share the x2 window -> smem broadcast/dedup)
    const int cchunk = tid / NTILE;          // 0 or 1 (c in [cchunk*64, +64))
    const int tile   = tid - cchunk * NTILE; // 0..131
    const int wgi    = tile / 11;            // 0..11  -> w0
    const int dg     = tile - wgi * 11;      // 0..10  -> dx0 (dg=10: only dx=80 valid)
    const int w0     = wgi * 8;
    const int dx0    = dg * 8;

    u64 acc[8][4];
#pragma unroll
    for (int d = 0; d < 8; ++d)
#pragma unroll
        for (int j = 0; j < 4; ++j) acc[d][j] = 0ull;

    const float* p1 = s1 + w0;              // 32B-aligned
    const float* p2 = s2 + w0 + dx0;        // 32B-aligned
    const int cb = cchunk * 64;

#pragma unroll 2
    for (int cc = 0; cc < 64; ++cc) {
        const float* r1 = p1 + (size_t)(cb + cc) * W;
        const float* r2 = p2 + (size_t)(cb + cc) * WPS;

        const float4 a0 = *(const float4*)(r1);
        const float4 a1 = *(const float4*)(r1 + 4);
        const float4 b0 = *(const float4*)(r2);
        const float4 b1 = *(const float4*)(r2 + 4);
        const float4 b2 = *(const float4*)(r2 + 8);
        const float4 b3 = *(const float4*)(r2 + 12);

        u64 A[4];
        A[0] = pack2(a0.x, a0.y); A[1] = pack2(a0.z, a0.w);
        A[2] = pack2(a1.x, a1.y); A[3] = pack2(a1.z, a1.w);

        const float bb[16] = {b0.x, b0.y, b0.z, b0.w,
                              b1.x, b1.y, b1.z, b1.w,
                              b2.x, b2.y, b2.z, b2.w,
                              b3.x, b3.y, b3.z, b3.w};
        u64 B[8], S[7];
#pragma unroll
        for (int k = 0; k < 8; ++k) B[k] = pack2(bb[2 * k], bb[2 * k + 1]);
#pragma unroll
        for (int k = 0; k < 7; ++k) S[k] = pack2(bb[2 * k + 1], bb[2 * k + 2]);

        // acc[d][j] (w pair 2j,2j+1): even d -> aligned pair B[d/2+j],
        //                             odd  d -> shifted pair S[d>>1 + j]
#pragma unroll
        for (int d = 0; d < 8; ++d) {
#pragma unroll
            for (int j = 0; j < 4; ++j) {
                const u64 op = (d & 1) ? S[(d >> 1) + j] : B[(d >> 1) + j];
                fma2(acc[d][j], A[j], op);
            }
        }
    }

    // ---- 2-way c-chunk reduction via smem (reuse s1/s2 region) ----
    __syncthreads();
    float* red = sm;   // layout [64 values][NTILE] -> conflict-free (lanes = consecutive tiles)

    if (cchunk == 1) {
#pragma unroll
        for (int d = 0; d < 8; ++d)
#pragma unroll
            for (int j = 0; j < 4; ++j) {
                const float2 f = unpack2(acc[d][j]);
                red[(d * 8 + 2 * j)     * NTILE + tile] = f.x;
                red[(d * 8 + 2 * j + 1) * NTILE + tile] = f.y;
            }
    }
    __syncthreads();

    if (cchunk == 0) {
        const float scale = 0.08838834764831843f;   // 1/sqrt(128)
#pragma unroll
        for (int d = 0; d < 8; ++d) {
            const int dx = dx0 + d;
            if (dx < KD) {
                float o[8];
#pragma unroll
                for (int j = 0; j < 4; ++j) {
                    const float2 f = unpack2(acc[d][j]);
                    o[2 * j]     = f.x;
                    o[2 * j + 1] = f.y;
                }
#pragma unroll
                for (int k = 0; k < 8; ++k)
                    o[k] = (o[k] + red[(d * 8 + k) * NTILE + tile]) * scale;

                const size_t off =
                    (((size_t)b * (KD * KD) + (size_t)(dy * KD + dx)) * H + h) * W + w0;
                float4 v0, v1;
                v0.x = o[0]; v0.y = o[1]; v0.z = o[2]; v0.w = o[3];
                v1.x = o[4]; v1.y = o[5]; v1.z = o[6]; v1.w = o[7];
                *(float4*)(out + off)     = v0;
                *(float4*)(out + off + 4) = v1;
            }
        }
    }
}

extern "C" void kernel_launch(void* const* d_in, const int* in_sizes, int n_in,
                              void* d_out, int out_size)
{
    const float* x1 = (const float*)d_in[0];
    const float* x2 = (const float*)d_in[1];
    float* out = (float*)d_out;

    cudaFuncSetAttribute(corr_kernel, cudaFuncAttributeMaxDynamicSharedMemorySize, SMEM_BYTES);

    dim3 grid(KD, H, 2);     // (dy, h, b)
    corr_kernel<<<grid, NT, SMEM_BYTES>>>(x1, x2, out);
}